// round 2
// baseline (speedup 1.0000x reference)
#include <cuda_runtime.h>
#include <math.h>

#define B 64
#define P 8732
#define NOBJ 16
#define NC 81
#define THRESH 0.5f
#define CHUNKS_PER_B 273           // ceil(8732/32)
#define NPART (B*CHUNKS_PER_B)

// ---------------- scratch (device globals; no allocs allowed) ----------------
__device__ float              g_overlap[B*P];
__device__ int                g_tidx[B*P];
__device__ float              g_mine[B*P];
__device__ unsigned long long g_bestprior[B*NOBJ];

__device__ float g_part_lossl[NPART];
__device__ float g_part_lcpos[NPART];
__device__ int   g_part_npos[NPART];

__device__ float g_lossl_b[B];
__device__ float g_lcpos_b[B];
__device__ float g_lneg_b[B];
__device__ int   g_npos_b[B];

// ---------------- helpers ----------------
__device__ __forceinline__ float smooth_l1(float x) {
    float ax = fabsf(x);
    return (ax < 1.0f) ? 0.5f * x * x : ax - 0.5f;
}

// ---------------- kernel 0: zero best-prior keys ----------------
__global__ void k_init() {
    int i = threadIdx.x;
    if (i < B * NOBJ) g_bestprior[i] = 0ULL;
}

// ---------------- kernel 1: matching (IoU) ----------------
// grid (ceil(P/256), B), block 256
__global__ void k_match(const float* __restrict__ priors,
                        const float* __restrict__ targets) {
    int b = blockIdx.y;
    int p = blockIdx.x * 256 + threadIdx.x;
    int lane = threadIdx.x & 31;
    int warp = threadIdx.x >> 5;

    __shared__ float s_t[NOBJ * 5];
    __shared__ unsigned long long s_wkey[8][NOBJ];

    if (threadIdx.x < NOBJ * 5) s_t[threadIdx.x] = targets[b * NOBJ * 5 + threadIdx.x];
    __syncthreads();

    bool valid = (p < P);
    float px1 = 0.f, py1 = 0.f, px2 = 0.f, py2 = 0.f, pa = 0.f;
    if (valid) {
        float4 pr = *(const float4*)(priors + p * 4);
        px1 = pr.x - pr.z * 0.5f; py1 = pr.y - pr.w * 0.5f;
        px2 = pr.x + pr.z * 0.5f; py2 = pr.y + pr.w * 0.5f;
        pa  = (px2 - px1) * (py2 - py1);
    }

    float bestv = -1.0f; int besti = 0;
    #pragma unroll
    for (int t = 0; t < NOBJ; t++) {
        float tx1 = s_t[t*5+0], ty1 = s_t[t*5+1], tx2 = s_t[t*5+2], ty2 = s_t[t*5+3];
        float ix1 = fmaxf(tx1, px1), iy1 = fmaxf(ty1, py1);
        float ix2 = fminf(tx2, px2), iy2 = fminf(ty2, py2);
        float iw = fmaxf(ix2 - ix1, 0.f), ih = fmaxf(iy2 - iy1, 0.f);
        float inter = iw * ih;
        float ta = (tx2 - tx1) * (ty2 - ty1);
        float iou = inter / (ta + pa - inter);
        if (valid && iou > bestv) { bestv = iou; besti = t; }
        // packed key: high=float bits (iou>=0), low = ~p so ties pick smallest p
        unsigned long long key = valid
            ? ((((unsigned long long)__float_as_uint(iou)) << 32) |
               (unsigned long long)(0xFFFFFFFFu - (unsigned)p))
            : 0ULL;
        #pragma unroll
        for (int s = 16; s > 0; s >>= 1) {
            unsigned long long o = __shfl_xor_sync(0xffffffffu, key, s);
            if (o > key) key = o;
        }
        if (lane == 0) s_wkey[warp][t] = key;
    }

    if (valid) {
        g_overlap[b * P + p] = bestv;
        g_tidx[b * P + p]    = besti;
    }
    __syncthreads();

    if (threadIdx.x < NOBJ) {
        unsigned long long k = 0ULL;
        #pragma unroll
        for (int w = 0; w < 8; w++) {
            unsigned long long v = s_wkey[w][threadIdx.x];
            if (v > k) k = v;
        }
        atomicMax(&g_bestprior[b * NOBJ + threadIdx.x], k);
    }
}

// ---------------- kernel 2: force best-prior matches (scatter order = j asc) --
__global__ void k_force() {
    int b = threadIdx.x;
    if (b < B) {
        for (int j = 0; j < NOBJ; j++) {
            unsigned long long key = g_bestprior[b * NOBJ + j];
            unsigned p = 0xFFFFFFFFu - (unsigned)(key & 0xFFFFFFFFull);
            g_overlap[b * P + p] = 2.0f;
            g_tidx[b * P + p]    = j;
        }
    }
}

// ---------------- kernel 3: main heavy kernel (warp per prior) ----------------
// grid B*CHUNKS_PER_B, block 256 (8 warps, 4 priors each)
__global__ void k_main(const float* __restrict__ loc,
                       const float* __restrict__ conf,
                       const float* __restrict__ priors,
                       const float* __restrict__ targets) {
    int chunk = blockIdx.x % CHUNKS_PER_B;
    int b     = blockIdx.x / CHUNKS_PER_B;
    int warp  = threadIdx.x >> 5;
    int lane  = threadIdx.x & 31;

    __shared__ float s_lossl[8], s_lcpos[8];
    __shared__ int   s_np[8];

    float w_lossl = 0.f, w_lcpos = 0.f;
    int   w_np = 0;

    for (int i = 0; i < 4; i++) {
        int p = chunk * 32 + warp * 4 + i;
        if (p >= P) break;

        const float* row = conf + ((size_t)b * P + p) * NC;
        float v0 = __ldg(row + lane);
        float v1 = __ldg(row + 32 + lane);
        float v2 = (lane < 17) ? __ldg(row + 64 + lane) : -1e30f;

        float m = fmaxf(fmaxf(v0, v1), v2);
        #pragma unroll
        for (int s = 16; s > 0; s >>= 1) m = fmaxf(m, __shfl_xor_sync(0xffffffffu, m, s));
        float e = __expf(v0 - m) + __expf(v1 - m) + ((lane < 17) ? __expf(v2 - m) : 0.f);
        #pragma unroll
        for (int s = 16; s > 0; s >>= 1) e += __shfl_xor_sync(0xffffffffu, e, s);
        float lse = m + __logf(e);

        float ov = __ldg(&g_overlap[b * P + p]);  // same addr: broadcast
        int   t  = __ldg(&g_tidx[b * P + p]);
        bool  pos = (ov >= THRESH);
        int   ct = 0;
        if (pos) ct = (int)__ldg(&targets[(b * NOBJ + t) * 5 + 4]) + 1;

        float src = (ct < 32) ? v0 : ((ct < 64) ? v1 : v2);
        float gathered = __shfl_sync(0xffffffffu, src, ct & 31);
        float lc   = lse - gathered;
        float mine = pos ? 0.f : lc;

        if (lane == 0) {
            g_mine[b * P + p] = mine;
            if (pos) {
                w_np++;
                w_lcpos += lc;
                // encode matched truth vs prior, then smooth-L1 vs loc_data
                float4 pr = *(const float4*)(priors + p * 4);
                const float* tr = targets + (b * NOBJ + t) * 5;
                float mx1 = tr[0], my1 = tr[1], mx2 = tr[2], my2 = tr[3];
                float gcx = ((mx1 + mx2) * 0.5f - pr.x) / (0.1f * pr.z);
                float gcy = ((my1 + my2) * 0.5f - pr.y) / (0.1f * pr.w);
                float gw  = __logf((mx2 - mx1) / pr.z) * (1.0f / 0.2f);
                float gh  = __logf((my2 - my1) / pr.w) * (1.0f / 0.2f);
                const float* ld = loc + ((size_t)b * P + p) * 4;
                w_lossl += smooth_l1(ld[0] - gcx) + smooth_l1(ld[1] - gcy)
                         + smooth_l1(ld[2] - gw)  + smooth_l1(ld[3] - gh);
            }
        }
    }

    if (lane == 0) { s_lossl[warp] = w_lossl; s_lcpos[warp] = w_lcpos; s_np[warp] = w_np; }
    __syncthreads();
    if (threadIdx.x == 0) {
        float ll = 0.f, lc = 0.f; int np = 0;
        #pragma unroll
        for (int w = 0; w < 8; w++) { ll += s_lossl[w]; lc += s_lcpos[w]; np += s_np[w]; }
        int idx = b * CHUNKS_PER_B + chunk;
        g_part_lossl[idx] = ll;
        g_part_lcpos[idx] = lc;
        g_part_npos[idx]  = np;
    }
}

// ---------------- kernel 4: per-batch reduction of partials ------------------
// grid B, block 256; fixed-order => deterministic
__global__ void k_redb() {
    int b = blockIdx.x;
    int tid = threadIdx.x, lane = tid & 31, warp = tid >> 5;
    __shared__ float s_ll[8], s_lc[8];
    __shared__ int   s_np[8];

    float ll = 0.f, lc = 0.f; int np = 0;
    for (int c = tid; c < CHUNKS_PER_B; c += 256) {
        int idx = b * CHUNKS_PER_B + c;
        ll += g_part_lossl[idx];
        lc += g_part_lcpos[idx];
        np += g_part_npos[idx];
    }
    #pragma unroll
    for (int s = 16; s > 0; s >>= 1) {
        ll += __shfl_xor_sync(0xffffffffu, ll, s);
        lc += __shfl_xor_sync(0xffffffffu, lc, s);
        np += __shfl_xor_sync(0xffffffffu, np, s);
    }
    if (lane == 0) { s_ll[warp] = ll; s_lc[warp] = lc; s_np[warp] = np; }
    __syncthreads();
    if (tid == 0) {
        float tll = 0.f, tlc = 0.f; int tnp = 0;
        #pragma unroll
        for (int w = 0; w < 8; w++) { tll += s_ll[w]; tlc += s_lc[w]; tnp += s_np[w]; }
        g_lossl_b[b] = tll;
        g_lcpos_b[b] = tlc;
        g_npos_b[b]  = tnp;
    }
}

// ---------------- kernel 5: hard-negative mining (exact radix top-k sum) -----
// grid B, block 1024
__global__ void k_neg() {
    int b = blockIdx.x;
    int tid = threadIdx.x, lane = tid & 31, warp = tid >> 5;

    __shared__ unsigned s_bits[P];       // ~35 KB
    __shared__ int  s_wcnt[32];
    __shared__ float s_wsum[32];
    __shared__ int  s_total;

    for (int i = tid; i < P; i += 1024)
        s_bits[i] = __float_as_uint(g_mine[b * P + i]);   // all values >= 0
    __syncthreads();

    int np = g_npos_b[b];
    int k = 3 * np; if (k > P - 1) k = P - 1;

    unsigned prefix = 0u;
    for (int bit = 31; bit >= 0; --bit) {
        unsigned cand = prefix | (1u << bit);
        int c = 0;
        for (int i = tid; i < P; i += 1024) c += (s_bits[i] >= cand);
        #pragma unroll
        for (int s = 16; s > 0; s >>= 1) c += __shfl_xor_sync(0xffffffffu, c, s);
        if (lane == 0) s_wcnt[warp] = c;
        __syncthreads();
        if (tid == 0) {
            int t = 0;
            #pragma unroll
            for (int w = 0; w < 32; w++) t += s_wcnt[w];
            s_total = t;
        }
        __syncthreads();
        if (s_total >= k) prefix = cand;
        __syncthreads();
    }
    // prefix == k-th largest value's bits (or 0 / all-ones edge cases handled by formula)

    int cg = 0; float sg = 0.f;
    for (int i = tid; i < P; i += 1024) {
        unsigned x = s_bits[i];
        if (x > prefix) { cg++; sg += __uint_as_float(x); }
    }
    #pragma unroll
    for (int s = 16; s > 0; s >>= 1) {
        cg += __shfl_xor_sync(0xffffffffu, cg, s);
        sg += __shfl_xor_sync(0xffffffffu, sg, s);
    }
    if (lane == 0) { s_wcnt[warp] = cg; s_wsum[warp] = sg; }
    __syncthreads();
    if (tid == 0) {
        int g = 0; float s = 0.f;
        #pragma unroll
        for (int w = 0; w < 32; w++) { g += s_wcnt[w]; s += s_wsum[w]; }
        g_lneg_b[b] = s + (float)(k - g) * __uint_as_float(prefix);
    }
}

// ---------------- kernel 6: final combine ----------------
__global__ void k_fin(float* __restrict__ out) {
    float lossl = 0.f, lossc = 0.f; int N = 0;
    for (int b = 0; b < B; b++) {
        lossl += g_lossl_b[b];
        lossc += g_lcpos_b[b] + g_lneg_b[b];
        N     += g_npos_b[b];
    }
    float fN = (float)N;
    out[0] = lossl / fN + lossc / fN;
}

// ---------------- launch ----------------
extern "C" void kernel_launch(void* const* d_in, const int* in_sizes, int n_in,
                              void* d_out, int out_size) {
    const float* loc     = (const float*)d_in[0];   // (B,P,4)
    const float* conf    = (const float*)d_in[1];   // (B,P,NC)
    const float* priors  = (const float*)d_in[2];   // (P,4)
    const float* targets = (const float*)d_in[3];   // (B,NOBJ,5)
    float* out = (float*)d_out;

    k_init<<<1, 1024>>>();
    k_match<<<dim3((P + 255) / 256, B), 256>>>(priors, targets);
    k_force<<<1, 64>>>();
    k_main<<<B * CHUNKS_PER_B, 256>>>(loc, conf, priors, targets);
    k_redb<<<B, 256>>>();
    k_neg<<<B, 1024>>>();
    k_fin<<<1, 1>>>(out);
}

// round 3
// speedup vs baseline: 1.7105x; 1.7105x over previous
#include <cuda_runtime.h>
#include <math.h>

#define B 64
#define P 8732
#define NOBJ 16
#define NC 81
#define THRESH 0.5f
#define RPB 128                 // conf rows per block in k_main
#define CPB 69                  // ceil(P/RPB)
#define NPART (B*CPB)

// ---------------- scratch (device globals; no allocs allowed) ----------------
__device__ float              g_overlap[B*P];
__device__ int                g_tidx[B*P];
__device__ float              g_mine[B*P];
__device__ unsigned long long g_bestprior[B*NOBJ];   // zero at load; k_force restores zeros

__device__ float g_part_lossl[NPART];
__device__ float g_part_lcpos[NPART];
__device__ int   g_part_npos[NPART];

__device__ float g_lossl_b[B];
__device__ float g_lossc_b[B];
__device__ int   g_npos_b[B];

__device__ __forceinline__ float smooth_l1(float x) {
    float ax = fabsf(x);
    return (ax < 1.0f) ? 0.5f * x * x : ax - 0.5f;
}

// ---------------- kernel 1: matching (IoU) ----------------
// grid (ceil(P/256), B), block 256
__global__ void k_match(const float* __restrict__ priors,
                        const float* __restrict__ targets) {
    int b = blockIdx.y;
    int p = blockIdx.x * 256 + threadIdx.x;
    int lane = threadIdx.x & 31;
    int warp = threadIdx.x >> 5;

    __shared__ float s_t[NOBJ * 5];
    __shared__ unsigned long long s_wkey[8][NOBJ];

    if (threadIdx.x < NOBJ * 5) s_t[threadIdx.x] = targets[b * NOBJ * 5 + threadIdx.x];
    __syncthreads();

    bool valid = (p < P);
    float px1 = 0.f, py1 = 0.f, px2 = 0.f, py2 = 0.f, pa = 0.f;
    if (valid) {
        float4 pr = *(const float4*)(priors + p * 4);
        px1 = pr.x - pr.z * 0.5f; py1 = pr.y - pr.w * 0.5f;
        px2 = pr.x + pr.z * 0.5f; py2 = pr.y + pr.w * 0.5f;
        pa  = (px2 - px1) * (py2 - py1);
    }

    float bestv = -1.0f; int besti = 0;
    #pragma unroll
    for (int t = 0; t < NOBJ; t++) {
        float tx1 = s_t[t*5+0], ty1 = s_t[t*5+1], tx2 = s_t[t*5+2], ty2 = s_t[t*5+3];
        float ix1 = fmaxf(tx1, px1), iy1 = fmaxf(ty1, py1);
        float ix2 = fminf(tx2, px2), iy2 = fminf(ty2, py2);
        float iw = fmaxf(ix2 - ix1, 0.f), ih = fmaxf(iy2 - iy1, 0.f);
        float inter = iw * ih;
        float ta = (tx2 - tx1) * (ty2 - ty1);
        float iou = inter / (ta + pa - inter);
        if (valid && iou > bestv) { bestv = iou; besti = t; }
        unsigned long long key = valid
            ? ((((unsigned long long)__float_as_uint(iou)) << 32) |
               (unsigned long long)(0xFFFFFFFFu - (unsigned)p))
            : 0ULL;
        #pragma unroll
        for (int s = 16; s > 0; s >>= 1) {
            unsigned long long o = __shfl_xor_sync(0xffffffffu, key, s);
            if (o > key) key = o;
        }
        if (lane == 0) s_wkey[warp][t] = key;
    }

    if (valid) {
        g_overlap[b * P + p] = bestv;
        g_tidx[b * P + p]    = besti;
    }
    __syncthreads();

    if (threadIdx.x < NOBJ) {
        unsigned long long k = 0ULL;
        #pragma unroll
        for (int w = 0; w < 8; w++) {
            unsigned long long v = s_wkey[w][threadIdx.x];
            if (v > k) k = v;
        }
        atomicMax(&g_bestprior[b * NOBJ + threadIdx.x], k);
    }
}

// ---------------- kernel 2: force best-prior matches + reset keys ------------
__global__ void k_force() {
    int b = threadIdx.x;
    if (b < B) {
        for (int j = 0; j < NOBJ; j++) {
            unsigned long long key = g_bestprior[b * NOBJ + j];
            g_bestprior[b * NOBJ + j] = 0ULL;   // restore for next graph replay
            unsigned p = 0xFFFFFFFFu - (unsigned)(key & 0xFFFFFFFFull);
            g_overlap[b * P + p] = 2.0f;
            g_tidx[b * P + p]    = j;
        }
    }
}

// ---------------- kernel 3: main heavy kernel (thread per prior, smem stage) -
// grid B*CPB, block RPB
__global__ void __launch_bounds__(RPB) k_main(const float* __restrict__ loc,
                                              const float* __restrict__ conf,
                                              const float* __restrict__ priors,
                                              const float* __restrict__ targets) {
    int blk = blockIdx.x;
    int b   = blk / CPB;
    int c   = blk % CPB;
    int p0  = c * RPB;
    int nrows = (p0 + RPB <= P) ? RPB : (P - p0);

    __shared__ float s_conf[RPB * NC];      // 41472 B
    __shared__ float s_ll[4], s_lc[4];
    __shared__ int   s_np[4];

    const float* base = conf + ((size_t)b * P + p0) * NC;
    int tid = threadIdx.x;

    if (nrows == RPB) {
        #pragma unroll
        for (int j = 0; j < NC; j++)
            s_conf[tid + j * RPB] = __ldg(base + tid + j * RPB);
    } else {
        int total = nrows * NC;
        for (int i = tid; i < total; i += RPB)
            s_conf[i] = __ldg(base + i);
    }
    __syncthreads();

    float lossl = 0.f, lcpos = 0.f; int np = 0;

    if (tid < nrows) {
        int p = p0 + tid;
        const float* row = s_conf + tid * NC;

        float sum = 0.f;
        #pragma unroll
        for (int j = 0; j < NC; j++) sum += __expf(row[j]);
        float lse = __logf(sum);

        float ov = g_overlap[b * P + p];
        int   t  = g_tidx[b * P + p];
        bool  pos = (ov >= THRESH);
        int   ct = 0;
        if (pos) ct = (int)__ldg(&targets[(b * NOBJ + t) * 5 + 4]) + 1;

        float lc = lse - row[ct];
        g_mine[b * P + p] = pos ? 0.f : lc;

        if (pos) {
            np = 1; lcpos = lc;
            float4 pr = *(const float4*)(priors + p * 4);
            const float* tr = targets + (b * NOBJ + t) * 5;
            float mx1 = tr[0], my1 = tr[1], mx2 = tr[2], my2 = tr[3];
            float gcx = ((mx1 + mx2) * 0.5f - pr.x) / (0.1f * pr.z);
            float gcy = ((my1 + my2) * 0.5f - pr.y) / (0.1f * pr.w);
            float gw  = __logf((mx2 - mx1) / pr.z) * 5.0f;
            float gh  = __logf((my2 - my1) / pr.w) * 5.0f;
            float4 ld = *(const float4*)(loc + ((size_t)b * P + p) * 4);
            lossl = smooth_l1(ld.x - gcx) + smooth_l1(ld.y - gcy)
                  + smooth_l1(ld.z - gw)  + smooth_l1(ld.w - gh);
        }
    }

    int lane = tid & 31, warp = tid >> 5;
    #pragma unroll
    for (int s = 16; s > 0; s >>= 1) {
        lossl += __shfl_xor_sync(0xffffffffu, lossl, s);
        lcpos += __shfl_xor_sync(0xffffffffu, lcpos, s);
        np    += __shfl_xor_sync(0xffffffffu, np, s);
    }
    if (lane == 0) { s_ll[warp] = lossl; s_lc[warp] = lcpos; s_np[warp] = np; }
    __syncthreads();
    if (tid == 0) {
        float a = 0.f, bb = 0.f; int n = 0;
        #pragma unroll
        for (int w = 0; w < 4; w++) { a += s_ll[w]; bb += s_lc[w]; n += s_np[w]; }
        g_part_lossl[blk] = a;
        g_part_lcpos[blk] = bb;
        g_part_npos[blk]  = n;
    }
}

// ---------------- kernel 4: per-batch reduce + hard-negative mining ----------
// grid B, block 1024. 3-level (11/11/10-bit) histogram top-k selection.
__global__ void __launch_bounds__(1024) k_negred() {
    int b = blockIdx.x;
    int tid = threadIdx.x, lane = tid & 31, warp = tid >> 5;

    __shared__ unsigned s_bits[P];          // 34928 B
    __shared__ int      s_hist[2048];       // 8192 B
    __shared__ int      s_gs[64];
    __shared__ float    s_fa[32], s_fb[32];
    __shared__ int      s_ia[32];
    __shared__ int      sh_k, sh_rem;
    __shared__ unsigned sh_pref;
    __shared__ float    sh_lcpos;

    // --- reduce k_main partials for this batch (CPB=69 entries) ---
    float ll = 0.f, lc = 0.f; int np = 0;
    if (tid < CPB) {
        int idx = b * CPB + tid;
        ll = g_part_lossl[idx]; lc = g_part_lcpos[idx]; np = g_part_npos[idx];
    }
    #pragma unroll
    for (int s = 16; s > 0; s >>= 1) {
        ll += __shfl_xor_sync(0xffffffffu, ll, s);
        lc += __shfl_xor_sync(0xffffffffu, lc, s);
        np += __shfl_xor_sync(0xffffffffu, np, s);
    }
    if (lane == 0) { s_fa[warp] = ll; s_fb[warp] = lc; s_ia[warp] = np; }
    __syncthreads();
    if (tid == 0) {
        float tll = 0.f, tlc = 0.f; int tnp = 0;
        #pragma unroll
        for (int w = 0; w < 32; w++) { tll += s_fa[w]; tlc += s_fb[w]; tnp += s_ia[w]; }
        g_lossl_b[b] = tll;
        g_npos_b[b]  = tnp;
        sh_lcpos = tlc;
        int k = 3 * tnp; if (k > P - 1) k = P - 1;
        sh_k = k;
        sh_rem = k;
        sh_pref = 0u;
    }

    // --- stage mine bits into smem (all >= 0 so float order == uint order) ---
    for (int i = tid; i < P; i += 1024)
        s_bits[i] = __float_as_uint(g_mine[b * P + i]);
    __syncthreads();

    int k = sh_k;
    if (k <= 0) {
        if (tid == 0) g_lossc_b[b] = sh_lcpos;
        return;
    }

    // --- 3-level histogram select of the k-th largest value ---
    const int shifts[3]   = {21, 10, 0};
    const unsigned msks[3] = {0x00000000u, 0xFFE00000u, 0xFFFFFC00u};
    const int nbuck[3]    = {2048, 2048, 1024};

    for (int lev = 0; lev < 3; lev++) {
        int nb = nbuck[lev];
        for (int i = tid; i < nb; i += 1024) s_hist[i] = 0;
        __syncthreads();
        unsigned msk = msks[lev], pref = sh_pref;
        int sh = shifts[lev];
        unsigned bmask = (unsigned)(nb - 1);
        for (int i = tid; i < P; i += 1024) {
            unsigned x = s_bits[i];
            if ((x & msk) == pref)
                atomicAdd(&s_hist[(x >> sh) & bmask], 1);
        }
        __syncthreads();
        int ng = nb >> 5;
        if (tid < ng) {
            int s = 0;
            #pragma unroll
            for (int j = 0; j < 32; j++) s += s_hist[tid * 32 + j];
            s_gs[tid] = s;
        }
        __syncthreads();
        if (tid == 0) {
            int rem = sh_rem;
            int acc = 0, g = ng - 1;
            for (; g > 0; g--) {
                if (acc + s_gs[g] >= rem) break;
                acc += s_gs[g];
            }
            int bkt = g * 32;
            for (int j = 31; j >= 0; j--) {
                int h = s_hist[g * 32 + j];
                if (acc + h >= rem) { bkt = g * 32 + j; break; }
                acc += h;
            }
            sh_rem = rem - acc;
            sh_pref = sh_pref | (((unsigned)bkt) << sh);
        }
        __syncthreads();
    }

    // --- exact top-k sum: sum(x > vk) + (k - cnt_gt) * vk ---
    unsigned vk = sh_pref;
    int cg = 0; float sg = 0.f;
    for (int i = tid; i < P; i += 1024) {
        unsigned x = s_bits[i];
        if (x > vk) { cg++; sg += __uint_as_float(x); }
    }
    #pragma unroll
    for (int s = 16; s > 0; s >>= 1) {
        cg += __shfl_xor_sync(0xffffffffu, cg, s);
        sg += __shfl_xor_sync(0xffffffffu, sg, s);
    }
    if (lane == 0) { s_ia[warp] = cg; s_fa[warp] = sg; }
    __syncthreads();
    if (tid == 0) {
        int g = 0; float s = 0.f;
        #pragma unroll
        for (int w = 0; w < 32; w++) { g += s_ia[w]; s += s_fa[w]; }
        float lneg = s + (float)(k - g) * __uint_as_float(vk);
        g_lossc_b[b] = sh_lcpos + lneg;
    }
}

// ---------------- kernel 5: final combine ----------------
__global__ void k_fin(float* __restrict__ out) {
    float lossl = 0.f, lossc = 0.f; int N = 0;
    for (int b = 0; b < B; b++) {
        lossl += g_lossl_b[b];
        lossc += g_lossc_b[b];
        N     += g_npos_b[b];
    }
    float fN = (float)N;
    out[0] = lossl / fN + lossc / fN;
}

// ---------------- launch ----------------
extern "C" void kernel_launch(void* const* d_in, const int* in_sizes, int n_in,
                              void* d_out, int out_size) {
    const float* loc     = (const float*)d_in[0];   // (B,P,4)
    const float* conf    = (const float*)d_in[1];   // (B,P,NC)
    const float* priors  = (const float*)d_in[2];   // (P,4)
    const float* targets = (const float*)d_in[3];   // (B,NOBJ,5)
    float* out = (float*)d_out;

    k_match<<<dim3((P + 255) / 256, B), 256>>>(priors, targets);
    k_force<<<1, 64>>>();
    k_main<<<B * CPB, RPB>>>(loc, conf, priors, targets);
    k_negred<<<B, 1024>>>();
    k_fin<<<1, 1>>>(out);
}